// round 17
// baseline (speedup 1.0000x reference)
#include <cuda_runtime.h>
#include <cstdint>

#define THREADS 256   // 64 query-quads x 4 candidate-chunks (2 warps/SMSP)
#define NCHUNK  4
#define QPT     4     // queries per thread
#define BLK     16    // candidates per tracking block

// Packed-fp32x2 helper (sm_103a). Per-lane .rn rounding bit-identical to scalar.
#define FMA2(d, a, b, c) \
    asm("fma.rn.f32x2 %0, %1, %2, %3;" : "=l"(d) : "l"(a), "l"(b), "l"(c))

__device__ __forceinline__ unsigned long long pack2(float lo, float hi) {
    unsigned long long r;
    asm("mov.b64 %0, {%1, %2};" : "=l"(r) : "f"(lo), "f"(hi));
    return r;
}
__device__ __forceinline__ void unpack2(float& lo, float& hi,
                                        unsigned long long v) {
    asm("mov.b64 {%0, %1}, %2;" : "=f"(lo), "=f"(hi) : "l"(v));
}

// Track 3 smallest block-min values (B1<=B2<=B3) + block ids of the 2 smallest.
#define TRACK(bm, jj, B1, B2, B3, J1, J2)         \
    {                                             \
        bool lt1 = (bm) < B1;                     \
        bool lt2 = (bm) < B2;                     \
        B3 = lt2 ? B2 : fminf(B3, (bm));          \
        B2 = lt1 ? B1 : fminf(B2, (bm));          \
        J2 = lt1 ? J1 : (lt2 ? (jj) : J2);        \
        B1 = fminf(B1, (bm));                     \
        J1 = lt1 ? (jj) : J1;                     \
    }

// Exact evaluation: bit-matches the JAX reference rounding (tx = -2x
// prescaled; power-of-2 scaling commutes exactly with fp32 rounding):
//   cross2 = fma(tz,az, fma(ty,ay, tx*ax));  e = (sq + w) + cross2
// Lexicographic (e, idx) min -> first-occurrence argmin.
__device__ __forceinline__ void exact_scan(const float4* __restrict__ sh,
                                           int lo, int hi,
                                           float ax, float ay, float az,
                                           float sq, float& be, int& bi) {
    for (int j = lo; j < hi; j++) {
        int pp = j >> 1, lane = j & 1;
        float4 A  = sh[2 * pp];
        float4 Bv = sh[2 * pp + 1];
        float tx = lane ? A.y  : A.x;
        float ty = lane ? A.w  : A.z;
        float tz = lane ? Bv.y : Bv.x;
        float cw = lane ? Bv.w : Bv.z;
        float cr = fmaf(tz, az, fmaf(ty, ay, __fmul_rn(tx, ax)));
        float ek = __fadd_rn(__fadd_rn(sq, cw), cr);
        if (ek < be || (ek == be && j < bi)) { be = ek; bi = j; }
    }
}

// Chamfer distance, both directions fused via blockIdx.z.
// smem pair-SoA, pre-scaled by -2 on xyz:
//   sh2[2p]   = ((-2x0,-2x1),(-2y0,-2y1))
//   sh2[2p+1] = ((-2z0,-2z1),( w0,  w1))   w = |c|^2, reference rounding
//
// 256 threads = 2 warps/SMSP (latency-bound regime: the LDS port is idle),
// FOUR queries per thread: each LDS.128 pair feeds 4 independent FMA2 chains
// (ILP to cover LDS latency) and is amortized over 8 evals (0.25 LDS/eval).
// FAST key: f = fma(-2x,ax, fma(-2y,ay, fma(-2z,az, w)))  [3 FMA2 / 2 evals]
// tracked at 16-candidate blocks (3 smallest block mins + 2 block ids).
// EXACT repair: |f-(e-sq)| <= ~8 roundings << eps = 2e-5*sq+4e-5, so the
// exact argmin provably lies in block J1 (plus J2 if B2<=B1+eps); if even
// B3<=B1+eps (P~4e-4) the whole 2048-candidate chunk is rescanned exactly.
__global__ __launch_bounds__(THREADS, 1)
void chamfer_kernel(const float* __restrict__ xyz1,
                    const float* __restrict__ xyz2,
                    float* __restrict__ out,
                    int N, int M, int B) {
    extern __shared__ float4 sh[];
    __shared__ float2 red[QPT][THREADS];   // per-query-slot (best, idx)

    const int dir = blockIdx.z;
    const int b   = blockIdx.y;

    const float* q;
    const float* c;
    int Nq, Nc;
    float* dist_out;
    float* idx_out;
    if (dir == 0) {
        q = xyz1; c = xyz2; Nq = N; Nc = M;
        dist_out = out;                                        // dist1
        idx_out  = out + (size_t)B * (N + M);                  // idx1
    } else {
        q = xyz2; c = xyz1; Nq = M; Nc = N;
        dist_out = out + (size_t)B * N;                        // dist2
        idx_out  = out + (size_t)B * (N + M) + (size_t)B * N;  // idx2
    }

    // ---- fill shared memory: (-2x,-2y,-2z, w), w with reference rounding ---
    const float* cb = c + (size_t)b * Nc * 3;
    const int npairs = Nc >> 1;
    for (int p = threadIdx.x; p < npairs; p += THREADS) {
        float x0 = cb[6 * p + 0], y0 = cb[6 * p + 1], z0 = cb[6 * p + 2];
        float x1 = cb[6 * p + 3], y1 = cb[6 * p + 4], z1 = cb[6 * p + 5];
        float w0 = __fadd_rn(__fadd_rn(__fmul_rn(x0, x0), __fmul_rn(y0, y0)),
                             __fmul_rn(z0, z0));
        float w1 = __fadd_rn(__fadd_rn(__fmul_rn(x1, x1), __fmul_rn(y1, y1)),
                             __fmul_rn(z1, z1));
        sh[2 * p]     = make_float4(-2.0f * x0, -2.0f * x1,
                                    -2.0f * y0, -2.0f * y1);
        sh[2 * p + 1] = make_float4(-2.0f * z0, -2.0f * z1, w0, w1);
    }
    __syncthreads();

    const ulonglong2* sh2 = reinterpret_cast<const ulonglong2*>(sh);

    const int g     = threadIdx.x & 63;    // query-quad id (0..63)
    const int chunk = threadIdx.x >> 6;    // candidate chunk (0..3)

    float ax[QPT], ay[QPT], az[QPT], sq[QPT];
    unsigned long long AX[QPT], AY[QPT], AZ[QPT];
#pragma unroll
    for (int k = 0; k < QPT; k++) {
        const int lane = QPT * g + k;
        const int i = lane * gridDim.x + blockIdx.x;   // interleaved, balanced
        const int iq = (i < Nq) ? i : 0;
        const float* qpt = q + ((size_t)b * Nq + iq) * 3;
        ax[k] = qpt[0]; ay[k] = qpt[1]; az[k] = qpt[2];
        sq[k] = __fadd_rn(__fadd_rn(__fmul_rn(ax[k], ax[k]),
                                    __fmul_rn(ay[k], ay[k])),
                          __fmul_rn(az[k], az[k]));
        AX[k] = pack2(ax[k], ax[k]); AY[k] = pack2(ay[k], ay[k]);
        AZ[k] = pack2(az[k], az[k]);
    }

    const int csz   = Nc / NCHUNK;         // 2048
    const int cbase = chunk * csz;

    const float INF = 3.402823466e38f;
    float b1[QPT], b2[QPT], b3[QPT];
    int   j1[QPT], j2[QPT];
#pragma unroll
    for (int k = 0; k < QPT; k++) {
        b1[k] = INF; b2[k] = INF; b3[k] = INF; j1[k] = cbase; j2[k] = cbase;
    }

    for (int j = cbase; j < cbase + csz; j += BLK) {
        float f[QPT][8];                   // pairwise mins (16 cands -> 8)
#pragma unroll
        for (int p = 0; p < 8; p++) {
            ulonglong2 A2 = sh2[j + 2 * p];      // (-2x pair),(-2y pair)
            ulonglong2 B2 = sh2[j + 2 * p + 1];  // (-2z pair),( w pair )
#pragma unroll
            for (int k = 0; k < QPT; k++) {
                unsigned long long u0, u1, u2;
                float lo, hi;
                FMA2(u0, B2.x, AZ[k], B2.y);     // fma(-2z,az, w)
                FMA2(u1, A2.y, AY[k], u0);       // fma(-2y,ay, .)
                FMA2(u2, A2.x, AX[k], u1);       // fma(-2x,ax, .)
                unpack2(lo, hi, u2);
                f[k][p] = fminf(lo, hi);
            }
        }
#pragma unroll
        for (int k = 0; k < QPT; k++) {
            float m01 = fminf(f[k][0], f[k][1]);
            float m23 = fminf(f[k][2], f[k][3]);
            float m45 = fminf(f[k][4], f[k][5]);
            float m67 = fminf(f[k][6], f[k][7]);
            float bm  = fminf(fminf(m01, m23), fminf(m45, m67));
            TRACK(bm, j, b1[k], b2[k], b3[k], j1[k], j2[k]);
        }
    }

    // ---- exact repair over the certified candidate set ---------------------
#pragma unroll
    for (int k = 0; k < QPT; k++) {
        const float eps = fmaf(sq[k], 2e-5f, 4e-5f);
        float be = INF;
        int   bi = 0;
        if (b3[k] <= __fadd_rn(b1[k], eps)) {
            exact_scan(sh, cbase, cbase + csz, ax[k], ay[k], az[k], sq[k],
                       be, bi);
        } else {
            exact_scan(sh, j1[k], j1[k] + BLK, ax[k], ay[k], az[k], sq[k],
                       be, bi);
            if (b2[k] <= __fadd_rn(b1[k], eps))
                exact_scan(sh, j2[k], j2[k] + BLK, ax[k], ay[k], az[k], sq[k],
                           be, bi);
        }
        red[k][threadIdx.x] = make_float2(be, (float)bi);
    }
    __syncthreads();

    // ---- merge the 4 chunks; ascending chunk order, strict < keeps the
    //      earliest chunk (smaller candidate index) on exact ties ----------
    {
        const int l  = threadIdx.x;        // query lane 0..255
        const int qi = l * gridDim.x + blockIdx.x;
        if (qi < Nq) {
            const int qk = l & (QPT - 1);  // query slot within the quad
            const int gg = l / QPT;        // quad id
            float2 r = red[qk][gg];        // chunk 0
#pragma unroll
            for (int cth = 1; cth < NCHUNK; cth++) {
                float2 rc = red[qk][cth * 64 + gg];
                if (rc.x < r.x) r = rc;
            }
            dist_out[(size_t)b * Nq + qi] = r.x;
            idx_out [(size_t)b * Nq + qi] = r.y;
        }
    }
}

extern "C" void kernel_launch(void* const* d_in, const int* in_sizes, int n_in,
                              void* d_out, int out_size) {
    const float* xyz1 = (const float*)d_in[0];
    const float* xyz2 = (const float*)d_in[1];
    float* out = (float*)d_out;

    const int B = 2;
    const int N = in_sizes[0] / (3 * B);
    const int M = in_sizes[1] / (3 * B);
    const int maxNM = (N > M) ? N : M;

    const size_t shmem = (size_t)maxNM * sizeof(float4);  // 128 KB for 8192
    cudaFuncSetAttribute(chamfer_kernel,
                         cudaFuncAttributeMaxDynamicSharedMemorySize,
                         (int)shmem);

    // 37 * 2 * 2 = 148 CTAs: one per SM, queries interleaved for balance.
    dim3 grid(37, B, 2);
    chamfer_kernel<<<grid, THREADS, shmem>>>(xyz1, xyz2, out, N, M, B);
}